// round 14
// baseline (speedup 1.0000x reference)
#include <cuda_runtime.h>
#include <cuda_fp16.h>
#include <cstdint>

#define QN    2048
#define EN    256
#define TOTC  40
#define NB    8
#define LMAXC 5
#define NH    8
#define NTAB  2048

// ---------------- scratch ----------------
__device__ __half g_hidden[TOTC*QN*EN];
__device__ __half g_kp    [TOTC*QN*EN];
__device__ __half g_kpx   [TOTC*QN*EN];
__device__ __half g_vp    [TOTC*QN*EN];
__device__ __half g_qpA   [NB*QN*EN];
__device__ __half g_qpB   [NB*QN*EN];
__device__ __half g_ctx   [NB*QN*EN];
__device__ float  g_table [3*NTAB*EN];
__device__ float  g_trig  [NTAB*EN];
__device__ float  g_wcat  [EN*512];
__device__ float  g_bkp   [EN];
__device__ float  g_wowq  [EN*EN];
__device__ float  g_bqo   [EN];
__device__ float  g_freq  [EN];
__device__ int    g_cav_batch[TOTC];
__device__ int    g_cav_local[TOTC];
__device__ int    g_batch_n  [NB];
__device__ int    g_batch_off[NB];

// ---------------- setup ----------------
__global__ void setup_kernel(const long long* __restrict__ rl64) {
    int t = threadIdx.x;
    if (t == 0) {
        bool ok64 = true;
        for (int b = 0; b < NB; b++) {
            long long v = rl64[b];
            if (v < 1 || v > LMAXC) ok64 = false;
        }
        const int* rl32 = (const int*)rl64;
        int acc = 0;
        for (int c = 0; c < TOTC; c++) { g_cav_batch[c] = 0; g_cav_local[c] = 0; }
        for (int b = 0; b < NB; b++) {
            int n = ok64 ? (int)rl64[b] : rl32[b];
            if (n < 1) n = 1;
            if (n > LMAXC) n = LMAXC;
            g_batch_n[b] = n; g_batch_off[b] = acc;
            for (int l = 0; l < n; l++) {
                int c = acc + l;
                if (c < TOTC) { g_cav_batch[c] = b; g_cav_local[c] = l; }
            }
            acc += n;
        }
    }
    for (int j = t; j < EN; j += blockDim.x) {
        float ex = (2.0f * (float)(j >> 1)) / (float)EN;
        g_freq[j] = 6.283185307179586f * expf(-ex * 9.210340371976184f);
    }
}

// ---------------- trig table ----------------
__global__ void trig_kernel() {
    int idx = blockIdx.x * blockDim.x + threadIdx.x;
    if (idx >= NTAB * EN) return;
    int j = idx & (EN - 1);
    int i = idx >> 8;
    float t = (float)i * (1.0f / (float)(NTAB - 1));
    float a = t * g_freq[j];
    g_trig[idx] = (j & 1) ? __cosf(a) : __sinf(a);
}

// ---------------- fused weight precompute ----------------
__global__ void wpre_kernel(const float* __restrict__ in_w, const float* __restrict__ in_b,
                            const float* __restrict__ w2,   const float* __restrict__ b2,
                            const float* __restrict__ ow,   const float* __restrict__ ob) {
    __shared__ float sWk[EN];
    __shared__ float sWq[EN];
    __shared__ float red[EN];
    int n = blockIdx.x, j = threadIdx.x;
    sWk[j] = in_w[(size_t)(EN + n)*EN + j];
    sWq[j] = in_w[(size_t)n*EN + j];
    __syncthreads();
    {
        float a0=0.f,a1=0.f,a2=0.f,a3=0.f;
        #pragma unroll 4
        for (int m = 0; m < EN; m += 4) {
            a0 = fmaf(sWk[m+0], w2[(size_t)(m+0)*EN + j], a0);
            a1 = fmaf(sWk[m+1], w2[(size_t)(m+1)*EN + j], a1);
            a2 = fmaf(sWk[m+2], w2[(size_t)(m+2)*EN + j], a2);
            a3 = fmaf(sWk[m+3], w2[(size_t)(m+3)*EN + j], a3);
        }
        g_wcat[(size_t)n*512 + j]      = sWk[j];
        g_wcat[(size_t)n*512 + EN + j] = (a0+a1)+(a2+a3);
    }
    {
        float a0=0.f,a1=0.f,a2=0.f,a3=0.f;
        #pragma unroll 4
        for (int m = 0; m < EN; m += 4) {
            a0 = fmaf(sWq[m+0], ow[(size_t)(m+0)*EN + j], a0);
            a1 = fmaf(sWq[m+1], ow[(size_t)(m+1)*EN + j], a1);
            a2 = fmaf(sWq[m+2], ow[(size_t)(m+2)*EN + j], a2);
            a3 = fmaf(sWq[m+3], ow[(size_t)(m+3)*EN + j], a3);
        }
        g_wowq[(size_t)n*EN + j] = (a0+a1)+(a2+a3);
    }
    red[j] = sWk[j] * b2[j];
    __syncthreads();
    for (int s = 128; s > 0; s >>= 1) {
        if (j < s) red[j] += red[j + s];
        __syncthreads();
    }
    if (j == 0) g_bkp[n] = in_b[EN + n] + red[0];
    __syncthreads();
    red[j] = sWq[j] * ob[j];
    __syncthreads();
    for (int s = 128; s > 0; s >>= 1) {
        if (j < s) red[j] += red[j + s];
        __syncthreads();
    }
    if (j == 0) g_bqo[n] = red[0];
}

// ---------------- fused trans + bev lookup -> hidden fp16 ----------------
// block = 256 threads = 4 rows x 64 lane-groups
__global__ void bev_kernel(const float* __restrict__ rp, const float* __restrict__ ptm,
                           const float* __restrict__ b1) {
    const int row0 = blockIdx.x * 4;
    const int cav  = row0 >> 11;
    if (g_cav_local[cav] == 0 || g_batch_n[g_cav_batch[cav]] <= 1) return;
    __shared__ float str[4][3];
    const int t = threadIdx.x;
    if (t < 12) {
        int r = t / 3, d = t % 3;
        int idx = row0 + r;
        int b = g_cav_batch[cav], l = g_cav_local[cav];
        float r0 = rp[idx*3+0] * 281.6f - 140.8f;
        float r1 = rp[idx*3+1] *  80.0f -  40.0f;
        float r2 = rp[idx*3+2] *   4.0f -   3.0f;
        const float* T = ptm + (size_t)((b * LMAXC + l) * LMAXC) * 16 + d * 4;
        float z = fmaf(T[0], r0, fmaf(T[1], r1, fmaf(T[2], r2, T[3])));
        str[r][d] = 1.0f / (1.0f + expf(-z));
    }
    __syncthreads();
    const int r   = t >> 6;
    const int n4  = t & 63;
    const int row = row0 + r;
    float4 acc = *(const float4*)(b1 + n4*4);
    #pragma unroll
    for (int d = 0; d < 3; d++) {
        float tv = str[r][d];
        float u  = tv * (float)(NTAB - 1);
        int i0 = (int)u;
        if (i0 < 0) i0 = 0;
        if (i0 > NTAB-2) i0 = NTAB-2;
        float w = u - (float)i0;
        const float* rr = g_table + ((size_t)(d*NTAB + i0))*EN + n4*4;
        float4 a = *(const float4*)rr;
        float4 b = *(const float4*)(rr + EN);
        acc.x = fmaf(w, b.x - a.x, acc.x + a.x);
        acc.y = fmaf(w, b.y - a.y, acc.y + a.y);
        acc.z = fmaf(w, b.z - a.z, acc.z + a.z);
        acc.w = fmaf(w, b.w - a.w, acc.w + a.w);
    }
    __half2 h0 = __floats2half2_rn(fmaxf(acc.x,0.f), fmaxf(acc.y,0.f));
    __half2 h1 = __floats2half2_rn(fmaxf(acc.z,0.f), fmaxf(acc.w,0.f));
    uint2 pk = make_uint2(*(uint32_t*)&h0, *(uint32_t*)&h1);
    *(uint2*)&g_hidden[(size_t)row*EN + n4*4] = pk;
}

// ================= single-pass fp16 tensor-core GEMM (64x64 warp tiles) =================
__device__ __forceinline__ uint32_t s2u(const void* p) {
    uint32_t a;
    asm("{ .reg .u64 t; cvta.to.shared.u64 t, %1; cvt.u32.u64 %0, t; }" : "=r"(a) : "l"(p));
    return a;
}
__device__ __forceinline__ void ldm4(uint32_t* f, uint32_t addr) {
    asm volatile("ldmatrix.sync.aligned.m8n8.x4.shared.b16 {%0,%1,%2,%3}, [%4];"
        : "=r"(f[0]),"=r"(f[1]),"=r"(f[2]),"=r"(f[3]) : "r"(addr));
}
__device__ __forceinline__ void mmahf(float* c, const uint32_t* a, const uint32_t* b) {
    asm volatile("mma.sync.aligned.m16n8k16.row.col.f32.f16.f16.f32 "
        "{%0,%1,%2,%3}, {%4,%5,%6,%7}, {%8,%9}, {%0,%1,%2,%3};"
        : "+f"(c[0]),"+f"(c[1]),"+f"(c[2]),"+f"(c[3])
        : "r"(a[0]),"r"(a[1]),"r"(a[2]),"r"(a[3]), "r"(b[0]),"r"(b[1]));
}
__device__ __forceinline__ uint32_t pkhf(float a, float b) {
    __half2 t = __floats2half2_rn(a, b);
    return *(uint32_t*)&t;
}

#define TSTR 24
#define TSZ  (128*TSTR)
#define GSMEM (2*2*TSZ*2)     // 24576 B

// MODE 2:  vp   = x @ Wv^T + bv                          (neighbor cavs)
// MODE 3:  qpA  = x_ego @ Wq^T + bq                      (multi batches)
// MODE 6:  table = trig @ W1_d^T                         (bn -> d/nloc)
// MODE 7:  qpB  = nm*(ctx@wowq^T + bqo) + nm*(qpA-bq)+bq (multi batches)
// MODE 8:  out_ego = ctx@Wo^T + nm2*x_ego + (nm2+nm)*bo  (final, writes OUT)
// MODE 9:  kpx  = x @ Wk^T                               (neighbor cavs, no bias)
// MODE 10: kp   = hidden @ Wkk^T + kpx + bkp             (neighbor cavs)
template<int MODE, int KT>
__global__ __launch_bounds__(128, 2) void mma_gemm(const float* __restrict__ W,
                                                   const float* __restrict__ bias,
                                                   const float* __restrict__ X,
                                                   float* __restrict__ OUT) {
    extern __shared__ __align__(16) __half sm[];

    const int bm = blockIdx.x, bn = blockIdx.y;
    int cav = 0;
    float scale = 1.0f;
    int bofs = 0;
    if (MODE == 2 || MODE == 9 || MODE == 10) {
        cav = bm >> 4;
        if (g_cav_local[cav] == 0 || g_batch_n[g_cav_batch[cav]] <= 1) return;
    } else if (MODE == 3 || MODE == 7 || MODE == 8) {
        int batch = bm >> 4;
        int n = g_batch_n[batch];
        if (n <= 1) return;
        scale = (float)(n - 1);
        bofs = g_batch_off[batch];
    }
    const int t    = threadIdx.x;
    const int lane = t & 31, wid = t >> 5;
    const int wm   = wid & 1, wn = wid >> 1;
    const int m0   = bm * 128, n0 = bn * 128;
    const int lrow4 = t >> 2;
    const int lf4   = t & 3;

    const int aoff = (wm*64 + (lane & 7) + ((lane >> 3) & 1) * 8) * TSTR + (lane >> 4) * 8;
    const int woff = (wn*64 + (lane & 7) + (lane >> 4) * 8) * TSTR + ((lane >> 3) & 1) * 8;

    const uint32_t smb = s2u(sm);

    uint2  araw[4];
    float4 vw[4];
    auto ld = [&](int kt) {
        const int k0 = kt * 16 + lf4 * 4;
        #pragma unroll
        for (int rr = 0; rr < 4; rr++) {
            const int row = lrow4 + rr * 32;
            const int arow = m0 + row;
            if (MODE == 2 || MODE == 9) {
                int q = arow & (QN-1);
                const float* s = X + (size_t)q*(TOTC*EN) + cav*EN + k0;
                float4 v = *(const float4*)s;
                araw[rr] = make_uint2(pkhf(v.x, v.y), pkhf(v.z, v.w));
            } else if (MODE == 10) {
                araw[rr] = *(const uint2*)&g_hidden[(size_t)arow*EN + k0];
            } else if (MODE == 3) {
                int q = arow & (QN-1);
                const float* s = X + (size_t)q*(TOTC*EN) + bofs*EN + k0;
                float4 v = *(const float4*)s;
                araw[rr] = make_uint2(pkhf(v.x, v.y), pkhf(v.z, v.w));
            } else if (MODE == 6) {
                const float* s = g_trig + (size_t)arow*EN + k0;
                float4 v = *(const float4*)s;
                araw[rr] = make_uint2(pkhf(v.x, v.y), pkhf(v.z, v.w));
            } else {
                araw[rr] = *(const uint2*)&g_ctx[(size_t)arow*EN + k0];
            }
            const float* ws;
            if (MODE == 10)     ws = g_wcat + (size_t)(n0 + row)*512 + 256 + k0;
            else if (MODE == 6) {
                int d = bn >> 1, nloc = (bn & 1) * 128;
                ws = W + (size_t)(nloc + row)*768 + d*256 + k0;
            }
            else if (MODE == 7) ws = g_wowq + (size_t)(n0 + row)*EN + k0;
            else                ws = W + (size_t)(n0 + row)*EN + k0;
            vw[rr] = *(const float4*)ws;
        }
    };
    auto st = [&](int stage) {
        #pragma unroll
        for (int rr = 0; rr < 4; rr++) {
            const int eo = (lrow4 + rr*32) * TSTR + lf4 * 4;
            *(uint2*)&sm[(stage*2+0)*TSZ + eo] = araw[rr];
            uint2 wv = make_uint2(pkhf(vw[rr].x, vw[rr].y), pkhf(vw[rr].z, vw[rr].w));
            *(uint2*)&sm[(stage*2+1)*TSZ + eo] = wv;
        }
    };

    float acc[4][8][4] = {};

    ld(0); st(0);
    __syncthreads();
    for (int kt = 0; kt < KT; kt++) {
        if (kt + 1 < KT) ld(kt + 1);
        const int stage = kt & 1;
        const uint32_t bA = smb + (stage*2+0)*TSZ*2 + aoff*2;
        const uint32_t bW = smb + (stage*2+1)*TSZ*2 + woff*2;

        uint32_t A[4][4];
        #pragma unroll
        for (int ms = 0; ms < 4; ms++)
            ldm4(A[ms], bA + ms*16*TSTR*2);
        #pragma unroll
        for (int np = 0; np < 4; np++) {
            uint32_t B[4];
            ldm4(B, bW + np*16*TSTR*2);
            #pragma unroll
            for (int ms = 0; ms < 4; ms++) {
                mmahf(acc[ms][2*np],   A[ms], B);
                mmahf(acc[ms][2*np+1], A[ms], B+2);
            }
        }
        if (kt + 1 < KT) st(stage ^ 1);
        __syncthreads();
    }

    // epilogue
    #pragma unroll
    for (int ms = 0; ms < 4; ms++) {
        const int row = m0 + wm*64 + ms*16 + (lane >> 2);
        #pragma unroll
        for (int ns = 0; ns < 8; ns++) {
            const int nlocal = wn*64 + ns*8 + (lane & 3)*2;
            const int col = n0 + nlocal;
            #pragma unroll
            for (int h = 0; h < 2; h++) {
                const int r = row + h*8;
                float v0 = acc[ms][ns][2*h];
                float v1 = acc[ms][ns][2*h+1];
                if (MODE == 9) {
                    *(uint32_t*)&g_kpx[(size_t)r*EN + col] = pkhf(v0, v1);
                } else if (MODE == 10) {
                    const size_t o = (size_t)r*EN + col;
                    uint32_t pk = *(uint32_t*)&g_kpx[o];
                    float2 kx = __half22float2(*(__half2*)&pk);
                    *(uint32_t*)&g_kp[o] = pkhf(v0 + kx.x + g_bkp[col],
                                                v1 + kx.y + g_bkp[col+1]);
                } else if (MODE == 2) {
                    *(uint32_t*)&g_vp[(size_t)r*EN + col] = pkhf(v0 + bias[col], v1 + bias[col+1]);
                } else if (MODE == 3) {
                    *(uint32_t*)&g_qpA[(size_t)r*EN + col] = pkhf(v0 + bias[col], v1 + bias[col+1]);
                } else if (MODE == 6) {
                    int d = bn >> 1, nloc = (bn & 1) * 128;
                    float* dst = g_table + ((size_t)(d*NTAB + r))*EN + nloc + nlocal;
                    *(float2*)dst = make_float2(v0, v1);
                } else if (MODE == 7) {
                    const size_t o = (size_t)r*EN + col;
                    float q10 = __half2float(g_qpA[o]);
                    float q11 = __half2float(g_qpA[o+1]);
                    float bq0 = bias[col], bq1 = bias[col+1];
                    float o0 = scale*(v0 + g_bqo[col])   + scale*(q10 - bq0) + bq0;
                    float o1 = scale*(v1 + g_bqo[col+1]) + scale*(q11 - bq1) + bq1;
                    *(uint32_t*)&g_qpB[o] = pkhf(o0, o1);
                } else {
                    const float nm2 = scale * scale;
                    int q = r & (QN - 1);
                    const float* xr = X + (size_t)q*(TOTC*EN) + bofs*EN + col;
                    float o0 = v0 + nm2*xr[0] + (nm2 + scale)*bias[col];
                    float o1 = v1 + nm2*xr[1] + (nm2 + scale)*bias[col+1];
                    float* dst = OUT + ((size_t)q*TOTC + bofs)*EN + col;
                    *(float2*)dst = make_float2(o0, o1);
                }
            }
        }
    }
}

// ---------------- degenerate attention (fp16 inputs, fp32 math) ----------------
__global__ void attn_kernel(int it) {
    int w = (blockIdx.x * blockDim.x + threadIdx.x) >> 5;
    int lane = threadIdx.x & 31;
    if (w >= NB * QN * NH) return;
    int h  = w & 7;
    int bq = w >> 3;
    int b  = bq >> 11;
    int q  = bq & (QN - 1);
    int n  = g_batch_n[b];
    if (n <= 1) return;
    int nm  = n - 1;
    int off = g_batch_off[b];
    int col = h * 32 + lane;

    const __half* qp = (it == 0) ? g_qpA : g_qpB;
    float qv = __half2float(qp[(size_t)bq*EN + col]);
    float sc[LMAXC - 1];
    for (int m = 0; m < nm; m++) {
        int c = off + 1 + m;
        float p = qv * __half2float(g_kp[(size_t)(c*QN + q)*EN + col]);
        #pragma unroll
        for (int o = 16; o; o >>= 1) p += __shfl_xor_sync(0xffffffffu, p, o);
        sc[m] = p * 0.17677669529663687f;
    }
    float mx = -1e30f;
    for (int m = 0; m < nm; m++) mx = fmaxf(mx, sc[m]);
    float s = 0.0f, wt[LMAXC - 1];
    for (int m = 0; m < nm; m++) { wt[m] = __expf(sc[m] - mx); s += wt[m]; }
    float inv = 1.0f / s;
    float ctx = 0.0f;
    for (int m = 0; m < nm; m++) {
        int c = off + 1 + m;
        ctx = fmaf(wt[m] * inv, __half2float(g_vp[(size_t)(c*QN + q)*EN + col]), ctx);
    }
    const size_t o = (size_t)bq*EN + col;
    if (it == 0) {
        g_ctx[o] = __float2half(ctx);
    } else {
        float fnm = (float)nm;
        float old = __half2float(g_ctx[o]);
        g_ctx[o] = __float2half(fnm*fnm*old + fnm*ctx);
    }
}

// ---------------- launch (fork-join multi-stream) ----------------
extern "C" void kernel_launch(void* const* d_in, const int* in_sizes, int n_in,
                              void* d_out, int out_size) {
    const float*     x    = (const float*)d_in[0];
    const float*     rp   = (const float*)d_in[1];
    const float*     ptm  = (const float*)d_in[2];
    const long long* rl   = (const long long*)d_in[3];
    const float*     in_w = (const float*)d_in[4];
    const float*     in_b = (const float*)d_in[5];
    const float*     ow   = (const float*)d_in[6];
    const float*     ob   = (const float*)d_in[7];
    const float*     w1   = (const float*)d_in[8];
    const float*     b1   = (const float*)d_in[9];
    const float*     w2   = (const float*)d_in[10];
    const float*     b2   = (const float*)d_in[11];
    float* out = (float*)d_out;

    static cudaStream_t sB = nullptr, sC = nullptr, sD = nullptr;
    static cudaEvent_t  ev0 = nullptr, evB = nullptr, evC = nullptr, evX = nullptr;
    if (sB == nullptr) {
        cudaStreamCreateWithFlags(&sB, cudaStreamNonBlocking);
        cudaStreamCreateWithFlags(&sC, cudaStreamNonBlocking);
        cudaStreamCreateWithFlags(&sD, cudaStreamNonBlocking);
        cudaEventCreateWithFlags(&ev0, cudaEventDisableTiming);
        cudaEventCreateWithFlags(&evB, cudaEventDisableTiming);
        cudaEventCreateWithFlags(&evC, cudaEventDisableTiming);
        cudaEventCreateWithFlags(&evX, cudaEventDisableTiming);
    }

    dim3 gcav(TOTC*QN/128, 2);      // 640 x 2
    dim3 gego(NB*QN/128, 2);        // 128 x 2
    dim3 gtab(NTAB/128, 6);         // 16 x 6

    // main: setup then fork everything off ev0
    setup_kernel<<<1, 256>>>(rl);
    cudaEventRecord(ev0, 0);

    // stream D: bulk copy x -> out
    cudaStreamWaitEvent(sD, ev0, 0);
    cudaMemcpyAsync(out, x, (size_t)QN*TOTC*EN*sizeof(float),
                    cudaMemcpyDeviceToDevice, sD);
    cudaEventRecord(evX, sD);

    // stream B: vp + kpx + qpA (all read x + weights only)
    cudaStreamWaitEvent(sB, ev0, 0);
    mma_gemm<2,16><<<gcav, 128, GSMEM, sB>>>(in_w + 512*EN, in_b + 512, x, out);  // vp
    mma_gemm<9,16><<<gcav, 128, GSMEM, sB>>>(in_w + 256*EN, nullptr,    x, out);  // kpx
    mma_gemm<3,16><<<gego, 128, GSMEM, sB>>>(in_w,          in_b,       x, out);  // qpA
    cudaEventRecord(evB, sB);

    // stream C: fused weight precompute
    cudaStreamWaitEvent(sC, ev0, 0);
    wpre_kernel<<<EN, EN, 0, sC>>>(in_w, in_b, w2, b2, ow, ob);
    cudaEventRecord(evC, sC);

    // main: trig -> tableGEMM -> bev(fused trans) -> (join) kp
    trig_kernel<<<(NTAB*EN + 255)/256, 256>>>();
    mma_gemm<6,16><<<gtab, 128, GSMEM>>>(w1, nullptr, nullptr, nullptr);          // table
    bev_kernel<<<TOTC*QN/4, 256>>>(rp, ptm, b1);
    cudaStreamWaitEvent(0, evC, 0);
    cudaStreamWaitEvent(0, evB, 0);
    mma_gemm<10,16><<<gcav, 128, GSMEM>>>(nullptr, nullptr, x, out);              // kp = kpx + hidden@Wkk

    // shortened attention chain
    attn_kernel<<<NB*QN*NH*32/256, 256>>>(0);                                     // ctx1
    mma_gemm<7,16><<<gego, 128, GSMEM>>>(nullptr, in_b, x, out);                  // qpB
    attn_kernel<<<NB*QN*NH*32/256, 256>>>(1);                                     // cmix
    cudaStreamWaitEvent(0, evX, 0);
    mma_gemm<8,16><<<gego, 128, GSMEM>>>(ow, ob, x, out);                         // final -> out
}

// round 17
// speedup vs baseline: 1.0663x; 1.0663x over previous
#include <cuda_runtime.h>
#include <cuda_fp16.h>
#include <cstdint>

#define QN    2048
#define EN    256
#define TOTC  40
#define NB    8
#define LMAXC 5
#define NH    8
#define NTAB  1024

// ---------------- scratch ----------------
__device__ __half g_hidden[TOTC*QN*EN];
__device__ __half g_kp    [TOTC*QN*EN];
__device__ __half g_vp    [TOTC*QN*EN];
__device__ __half g_qpA   [NB*QN*EN];
__device__ __half g_qpB   [NB*QN*EN];
__device__ __half g_ctx   [NB*QN*EN];
__device__ float  g_table [3*NTAB*EN];
__device__ float  g_trig  [NTAB*EN];
__device__ float  g_wcat  [EN*512];
__device__ float  g_bkp   [EN];
__device__ float  g_wowq  [EN*EN];
__device__ float  g_bqo   [EN];
__device__ float  g_freq  [EN];
__device__ int    g_cav_batch[TOTC];
__device__ int    g_cav_local[TOTC];
__device__ int    g_batch_n  [NB];
__device__ int    g_batch_off[NB];

// ---------------- setup ----------------
__global__ void setup_kernel(const long long* __restrict__ rl64) {
    int t = threadIdx.x;
    if (t == 0) {
        bool ok64 = true;
        for (int b = 0; b < NB; b++) {
            long long v = rl64[b];
            if (v < 1 || v > LMAXC) ok64 = false;
        }
        const int* rl32 = (const int*)rl64;
        int acc = 0;
        for (int c = 0; c < TOTC; c++) { g_cav_batch[c] = 0; g_cav_local[c] = 0; }
        for (int b = 0; b < NB; b++) {
            int n = ok64 ? (int)rl64[b] : rl32[b];
            if (n < 1) n = 1;
            if (n > LMAXC) n = LMAXC;
            g_batch_n[b] = n; g_batch_off[b] = acc;
            for (int l = 0; l < n; l++) {
                int c = acc + l;
                if (c < TOTC) { g_cav_batch[c] = b; g_cav_local[c] = l; }
            }
            acc += n;
        }
    }
    for (int j = t; j < EN; j += blockDim.x) {
        float ex = (2.0f * (float)(j >> 1)) / (float)EN;
        g_freq[j] = 6.283185307179586f * expf(-ex * 9.210340371976184f);
    }
}

// ---------------- trig table ----------------
__global__ void trig_kernel() {
    int idx = blockIdx.x * blockDim.x + threadIdx.x;
    if (idx >= NTAB * EN) return;
    int j = idx & (EN - 1);
    int i = idx >> 8;
    float t = (float)i * (1.0f / (float)(NTAB - 1));
    float a = t * g_freq[j];
    g_trig[idx] = (j & 1) ? __cosf(a) : __sinf(a);
}

// ---------------- fused weight precompute (8-wide MLP) ----------------
__global__ void wpre_kernel(const float* __restrict__ in_w, const float* __restrict__ in_b,
                            const float* __restrict__ w2,   const float* __restrict__ b2,
                            const float* __restrict__ ow,   const float* __restrict__ ob) {
    __shared__ float sWk[EN];
    __shared__ float sWq[EN];
    __shared__ float red[EN];
    int n = blockIdx.x, j = threadIdx.x;
    sWk[j] = in_w[(size_t)(EN + n)*EN + j];
    sWq[j] = in_w[(size_t)n*EN + j];
    __syncthreads();
    {
        float a[8] = {};
        #pragma unroll 2
        for (int m = 0; m < EN; m += 8)
            #pragma unroll
            for (int u = 0; u < 8; u++)
                a[u] = fmaf(sWk[m+u], w2[(size_t)(m+u)*EN + j], a[u]);
        float acc = ((a[0]+a[1])+(a[2]+a[3])) + ((a[4]+a[5])+(a[6]+a[7]));
        g_wcat[(size_t)n*512 + j]      = sWk[j];
        g_wcat[(size_t)n*512 + EN + j] = acc;
    }
    {
        float a[8] = {};
        #pragma unroll 2
        for (int m = 0; m < EN; m += 8)
            #pragma unroll
            for (int u = 0; u < 8; u++)
                a[u] = fmaf(sWq[m+u], ow[(size_t)(m+u)*EN + j], a[u]);
        g_wowq[(size_t)n*EN + j] = ((a[0]+a[1])+(a[2]+a[3])) + ((a[4]+a[5])+(a[6]+a[7]));
    }
    red[j] = sWk[j] * b2[j];
    __syncthreads();
    for (int s = 128; s > 0; s >>= 1) {
        if (j < s) red[j] += red[j + s];
        __syncthreads();
    }
    if (j == 0) g_bkp[n] = in_b[EN + n] + red[0];
    __syncthreads();
    red[j] = sWq[j] * ob[j];
    __syncthreads();
    for (int s = 128; s > 0; s >>= 1) {
        if (j < s) red[j] += red[j + s];
        __syncthreads();
    }
    if (j == 0) g_bqo[n] = red[0];
}

// ---------------- fused trans + bev lookup -> hidden fp16 ----------------
__global__ void bev_kernel(const float* __restrict__ rp, const float* __restrict__ ptm,
                           const float* __restrict__ b1) {
    const int row0 = blockIdx.x * 4;
    const int cav  = row0 >> 11;
    if (g_cav_local[cav] == 0 || g_batch_n[g_cav_batch[cav]] <= 1) return;
    __shared__ float str[4][3];
    const int t = threadIdx.x;
    if (t < 12) {
        int r = t / 3, d = t % 3;
        int idx = row0 + r;
        int b = g_cav_batch[cav], l = g_cav_local[cav];
        float r0 = rp[idx*3+0] * 281.6f - 140.8f;
        float r1 = rp[idx*3+1] *  80.0f -  40.0f;
        float r2 = rp[idx*3+2] *   4.0f -   3.0f;
        const float* T = ptm + (size_t)((b * LMAXC + l) * LMAXC) * 16 + d * 4;
        float z = fmaf(T[0], r0, fmaf(T[1], r1, fmaf(T[2], r2, T[3])));
        str[r][d] = 1.0f / (1.0f + expf(-z));
    }
    __syncthreads();
    const int r   = t >> 6;
    const int n4  = t & 63;
    const int row = row0 + r;
    float4 acc = *(const float4*)(b1 + n4*4);
    #pragma unroll
    for (int d = 0; d < 3; d++) {
        float tv = str[r][d];
        float u  = tv * (float)(NTAB - 1);
        int i0 = (int)u;
        if (i0 < 0) i0 = 0;
        if (i0 > NTAB-2) i0 = NTAB-2;
        float w = u - (float)i0;
        const float* rr = g_table + ((size_t)(d*NTAB + i0))*EN + n4*4;
        float4 a = *(const float4*)rr;
        float4 b = *(const float4*)(rr + EN);
        acc.x = fmaf(w, b.x - a.x, acc.x + a.x);
        acc.y = fmaf(w, b.y - a.y, acc.y + a.y);
        acc.z = fmaf(w, b.z - a.z, acc.z + a.z);
        acc.w = fmaf(w, b.w - a.w, acc.w + a.w);
    }
    __half2 h0 = __floats2half2_rn(fmaxf(acc.x,0.f), fmaxf(acc.y,0.f));
    __half2 h1 = __floats2half2_rn(fmaxf(acc.z,0.f), fmaxf(acc.w,0.f));
    uint2 pk = make_uint2(*(uint32_t*)&h0, *(uint32_t*)&h1);
    *(uint2*)&g_hidden[(size_t)row*EN + n4*4] = pk;
}

// ================= single-pass fp16 tensor-core GEMM (64x64 warp tiles) =================
__device__ __forceinline__ uint32_t s2u(const void* p) {
    uint32_t a;
    asm("{ .reg .u64 t; cvta.to.shared.u64 t, %1; cvt.u32.u64 %0, t; }" : "=r"(a) : "l"(p));
    return a;
}
__device__ __forceinline__ void ldm4(uint32_t* f, uint32_t addr) {
    asm volatile("ldmatrix.sync.aligned.m8n8.x4.shared.b16 {%0,%1,%2,%3}, [%4];"
        : "=r"(f[0]),"=r"(f[1]),"=r"(f[2]),"=r"(f[3]) : "r"(addr));
}
__device__ __forceinline__ void mmahf(float* c, const uint32_t* a, const uint32_t* b) {
    asm volatile("mma.sync.aligned.m16n8k16.row.col.f32.f16.f16.f32 "
        "{%0,%1,%2,%3}, {%4,%5,%6,%7}, {%8,%9}, {%0,%1,%2,%3};"
        : "+f"(c[0]),"+f"(c[1]),"+f"(c[2]),"+f"(c[3])
        : "r"(a[0]),"r"(a[1]),"r"(a[2]),"r"(a[3]), "r"(b[0]),"r"(b[1]));
}
__device__ __forceinline__ uint32_t pkhf(float a, float b) {
    __half2 t = __floats2half2_rn(a, b);
    return *(uint32_t*)&t;
}

#define TSTR 24
#define TSZ  (128*TSTR)
#define GSMEM (2*2*TSZ*2)

// MODE 1: kp (K=512)   MODE 2: vp   MODE 3: qpA   MODE 6: table
// MODE 7: qpB          MODE 8: final ego -> OUT
template<int MODE, int KT>
__global__ __launch_bounds__(128, 2) void mma_gemm(const float* __restrict__ W,
                                                   const float* __restrict__ bias,
                                                   const float* __restrict__ X,
                                                   float* __restrict__ OUT) {
    extern __shared__ __align__(16) __half sm[];

    const int bm = blockIdx.x, bn = blockIdx.y;
    int cav = 0;
    float scale = 1.0f;
    int bofs = 0;
    if (MODE == 1 || MODE == 2) {
        cav = bm >> 4;
        if (g_cav_local[cav] == 0 || g_batch_n[g_cav_batch[cav]] <= 1) return;
    } else if (MODE == 3 || MODE == 7 || MODE == 8) {
        int batch = bm >> 4;
        int n = g_batch_n[batch];
        if (n <= 1) return;
        scale = (float)(n - 1);
        bofs = g_batch_off[batch];
    }
    const int t    = threadIdx.x;
    const int lane = t & 31, wid = t >> 5;
    const int wm   = wid & 1, wn = wid >> 1;
    const int m0   = bm * 128, n0 = bn * 128;
    const int lrow4 = t >> 2;
    const int lf4   = t & 3;

    const int aoff = (wm*64 + (lane & 7) + ((lane >> 3) & 1) * 8) * TSTR + (lane >> 4) * 8;
    const int woff = (wn*64 + (lane & 7) + (lane >> 4) * 8) * TSTR + ((lane >> 3) & 1) * 8;

    const uint32_t smb = s2u(sm);

    uint2  araw[4];
    float4 vw[4];
    auto ld = [&](int kt) {
        const int k0 = kt * 16 + lf4 * 4;
        #pragma unroll
        for (int rr = 0; rr < 4; rr++) {
            const int row = lrow4 + rr * 32;
            const int arow = m0 + row;
            if (MODE == 1) {
                if (k0 < 256) {
                    int q = arow & (QN-1);
                    const float* s = X + (size_t)q*(TOTC*EN) + cav*EN + k0;
                    float4 v = *(const float4*)s;
                    araw[rr] = make_uint2(pkhf(v.x, v.y), pkhf(v.z, v.w));
                } else {
                    araw[rr] = *(const uint2*)&g_hidden[(size_t)arow*EN + (k0 - 256)];
                }
            } else if (MODE == 2) {
                int q = arow & (QN-1);
                const float* s = X + (size_t)q*(TOTC*EN) + cav*EN + k0;
                float4 v = *(const float4*)s;
                araw[rr] = make_uint2(pkhf(v.x, v.y), pkhf(v.z, v.w));
            } else if (MODE == 3) {
                int q = arow & (QN-1);
                const float* s = X + (size_t)q*(TOTC*EN) + bofs*EN + k0;
                float4 v = *(const float4*)s;
                araw[rr] = make_uint2(pkhf(v.x, v.y), pkhf(v.z, v.w));
            } else if (MODE == 6) {
                const float* s = g_trig + (size_t)arow*EN + k0;
                float4 v = *(const float4*)s;
                araw[rr] = make_uint2(pkhf(v.x, v.y), pkhf(v.z, v.w));
            } else {
                araw[rr] = *(const uint2*)&g_ctx[(size_t)arow*EN + k0];
            }
            const float* ws;
            if (MODE == 1)      ws = g_wcat + (size_t)(n0 + row)*512 + k0;
            else if (MODE == 6) {
                int d = bn >> 1, nloc = (bn & 1) * 128;
                ws = W + (size_t)(nloc + row)*768 + d*256 + k0;
            }
            else if (MODE == 7) ws = g_wowq + (size_t)(n0 + row)*EN + k0;
            else                ws = W + (size_t)(n0 + row)*EN + k0;
            vw[rr] = *(const float4*)ws;
        }
    };
    auto st = [&](int stage) {
        #pragma unroll
        for (int rr = 0; rr < 4; rr++) {
            const int eo = (lrow4 + rr*32) * TSTR + lf4 * 4;
            *(uint2*)&sm[(stage*2+0)*TSZ + eo] = araw[rr];
            uint2 wv = make_uint2(pkhf(vw[rr].x, vw[rr].y), pkhf(vw[rr].z, vw[rr].w));
            *(uint2*)&sm[(stage*2+1)*TSZ + eo] = wv;
        }
    };

    float acc[4][8][4] = {};

    ld(0); st(0);
    __syncthreads();
    for (int kt = 0; kt < KT; kt++) {
        if (kt + 1 < KT) ld(kt + 1);
        const int stage = kt & 1;
        const uint32_t bA = smb + (stage*2+0)*TSZ*2 + aoff*2;
        const uint32_t bW = smb + (stage*2+1)*TSZ*2 + woff*2;

        uint32_t A[4][4];
        #pragma unroll
        for (int ms = 0; ms < 4; ms++)
            ldm4(A[ms], bA + ms*16*TSTR*2);
        #pragma unroll
        for (int np = 0; np < 4; np++) {
            uint32_t B[4];
            ldm4(B, bW + np*16*TSTR*2);
            #pragma unroll
            for (int ms = 0; ms < 4; ms++) {
                mmahf(acc[ms][2*np],   A[ms], B);
                mmahf(acc[ms][2*np+1], A[ms], B+2);
            }
        }
        if (kt + 1 < KT) st(stage ^ 1);
        __syncthreads();
    }

    // epilogue
    #pragma unroll
    for (int ms = 0; ms < 4; ms++) {
        const int row = m0 + wm*64 + ms*16 + (lane >> 2);
        #pragma unroll
        for (int ns = 0; ns < 8; ns++) {
            const int nlocal = wn*64 + ns*8 + (lane & 3)*2;
            const int col = n0 + nlocal;
            #pragma unroll
            for (int h = 0; h < 2; h++) {
                const int r = row + h*8;
                float v0 = acc[ms][ns][2*h];
                float v1 = acc[ms][ns][2*h+1];
                if (MODE == 1) {
                    *(uint32_t*)&g_kp[(size_t)r*EN + col] = pkhf(v0 + g_bkp[col], v1 + g_bkp[col+1]);
                } else if (MODE == 2) {
                    *(uint32_t*)&g_vp[(size_t)r*EN + col] = pkhf(v0 + bias[col], v1 + bias[col+1]);
                } else if (MODE == 3) {
                    *(uint32_t*)&g_qpA[(size_t)r*EN + col] = pkhf(v0 + bias[col], v1 + bias[col+1]);
                } else if (MODE == 6) {
                    int d = bn >> 1, nloc = (bn & 1) * 128;
                    float* dst = g_table + ((size_t)(d*NTAB + r))*EN + nloc + nlocal;
                    *(float2*)dst = make_float2(v0, v1);
                } else if (MODE == 7) {
                    const size_t o = (size_t)r*EN + col;
                    float q10 = __half2float(g_qpA[o]);
                    float q11 = __half2float(g_qpA[o+1]);
                    float bq0 = bias[col], bq1 = bias[col+1];
                    float o0 = scale*(v0 + g_bqo[col])   + scale*(q10 - bq0) + bq0;
                    float o1 = scale*(v1 + g_bqo[col+1]) + scale*(q11 - bq1) + bq1;
                    *(uint32_t*)&g_qpB[o] = pkhf(o0, o1);
                } else {
                    const float nm2 = scale * scale;
                    int q = r & (QN - 1);
                    const float* xr = X + (size_t)q*(TOTC*EN) + bofs*EN + col;
                    float o0 = v0 + nm2*xr[0] + (nm2 + scale)*bias[col];
                    float o1 = v1 + nm2*xr[1] + (nm2 + scale)*bias[col+1];
                    float* dst = OUT + ((size_t)q*TOTC + bofs)*EN + col;
                    *(float2*)dst = make_float2(o0, o1);
                }
            }
        }
    }
}

// ---------------- degenerate attention (fp16 inputs, fp32 math) ----------------
__global__ void attn_kernel(int it) {
    int w = (blockIdx.x * blockDim.x + threadIdx.x) >> 5;
    int lane = threadIdx.x & 31;
    if (w >= NB * QN * NH) return;
    int h  = w & 7;
    int bq = w >> 3;
    int b  = bq >> 11;
    int q  = bq & (QN - 1);
    int n  = g_batch_n[b];
    if (n <= 1) return;
    int nm  = n - 1;
    int off = g_batch_off[b];
    int col = h * 32 + lane;

    const __half* qp = (it == 0) ? g_qpA : g_qpB;
    float qv = __half2float(qp[(size_t)bq*EN + col]);
    float sc[LMAXC - 1];
    for (int m = 0; m < nm; m++) {
        int c = off + 1 + m;
        float p = qv * __half2float(g_kp[(size_t)(c*QN + q)*EN + col]);
        #pragma unroll
        for (int o = 16; o; o >>= 1) p += __shfl_xor_sync(0xffffffffu, p, o);
        sc[m] = p * 0.17677669529663687f;
    }
    float mx = -1e30f;
    for (int m = 0; m < nm; m++) mx = fmaxf(mx, sc[m]);
    float s = 0.0f, wt[LMAXC - 1];
    for (int m = 0; m < nm; m++) { wt[m] = __expf(sc[m] - mx); s += wt[m]; }
    float inv = 1.0f / s;
    float ctx = 0.0f;
    for (int m = 0; m < nm; m++) {
        int c = off + 1 + m;
        ctx = fmaf(wt[m] * inv, __half2float(g_vp[(size_t)(c*QN + q)*EN + col]), ctx);
    }
    const size_t o = (size_t)bq*EN + col;
    if (it == 0) {
        g_ctx[o] = __float2half(ctx);
    } else {
        float fnm = (float)nm;
        float old = __half2float(g_ctx[o]);
        g_ctx[o] = __float2half(fnm*fnm*old + fnm*ctx);
    }
}

// ---------------- launch (fork-join multi-stream) ----------------
extern "C" void kernel_launch(void* const* d_in, const int* in_sizes, int n_in,
                              void* d_out, int out_size) {
    const float*     x    = (const float*)d_in[0];
    const float*     rp   = (const float*)d_in[1];
    const float*     ptm  = (const float*)d_in[2];
    const long long* rl   = (const long long*)d_in[3];
    const float*     in_w = (const float*)d_in[4];
    const float*     in_b = (const float*)d_in[5];
    const float*     ow   = (const float*)d_in[6];
    const float*     ob   = (const float*)d_in[7];
    const float*     w1   = (const float*)d_in[8];
    const float*     b1   = (const float*)d_in[9];
    const float*     w2   = (const float*)d_in[10];
    const float*     b2   = (const float*)d_in[11];
    float* out = (float*)d_out;

    static cudaStream_t sB = nullptr, sC = nullptr, sD = nullptr;
    static cudaEvent_t  ev0 = nullptr, evB = nullptr, evC = nullptr, evX = nullptr;
    if (sB == nullptr) {
        cudaStreamCreateWithFlags(&sB, cudaStreamNonBlocking);
        cudaStreamCreateWithFlags(&sC, cudaStreamNonBlocking);
        cudaStreamCreateWithFlags(&sD, cudaStreamNonBlocking);
        cudaEventCreateWithFlags(&ev0, cudaEventDisableTiming);
        cudaEventCreateWithFlags(&evB, cudaEventDisableTiming);
        cudaEventCreateWithFlags(&evC, cudaEventDisableTiming);
        cudaEventCreateWithFlags(&evX, cudaEventDisableTiming);
    }

    dim3 gcav(TOTC*QN/128, 2);
    dim3 gego(NB*QN/128, 2);
    dim3 gtab(NTAB/128, 6);

    setup_kernel<<<1, 256>>>(rl);
    cudaEventRecord(ev0, 0);

    cudaStreamWaitEvent(sD, ev0, 0);
    cudaMemcpyAsync(out, x, (size_t)QN*TOTC*EN*sizeof(float),
                    cudaMemcpyDeviceToDevice, sD);
    cudaEventRecord(evX, sD);

    cudaStreamWaitEvent(sB, ev0, 0);
    mma_gemm<2,16><<<gcav, 128, GSMEM, sB>>>(in_w + 512*EN, in_b + 512, x, out);
    mma_gemm<3,16><<<gego, 128, GSMEM, sB>>>(in_w, in_b, x, out);
    cudaEventRecord(evB, sB);

    cudaStreamWaitEvent(sC, ev0, 0);
    wpre_kernel<<<EN, EN, 0, sC>>>(in_w, in_b, w2, b2, ow, ob);
    cudaEventRecord(evC, sC);

    trig_kernel<<<(NTAB*EN + 255)/256, 256>>>();
    mma_gemm<6,16><<<gtab, 128, GSMEM>>>(w1, nullptr, nullptr, nullptr);
    bev_kernel<<<TOTC*QN/4, 256>>>(rp, ptm, b1);
    cudaStreamWaitEvent(0, evC, 0);
    mma_gemm<1,32><<<gcav, 128, GSMEM>>>(nullptr, nullptr, x, out);

    cudaStreamWaitEvent(0, evB, 0);
    attn_kernel<<<NB*QN*NH*32/256, 256>>>(0);
    mma_gemm<7,16><<<gego, 128, GSMEM>>>(nullptr, in_b, x, out);
    attn_kernel<<<NB*QN*NH*32/256, 256>>>(1);
    cudaStreamWaitEvent(0, evX, 0);
    mma_gemm<8,16><<<gego, 128, GSMEM>>>(ow, ob, x, out);
}